// round 15
// baseline (speedup 1.0000x reference)
#include <cuda_runtime.h>
#include <cuda_fp16.h>
#include <cstdint>

// ---------------------------------------------------------------------------
// GraphSAGE, 3 layers, mean aggregation, fp16 data / fp32 accumulation.
// Layers 0/1: agg = mean h[src]; h' = relu([h|agg] @ [Ws;Wn] + b)  (dual-A)
// Layer 2:    [y2|p2] = h2 @ [Wn2|Ws2]; out = p2 + b2 + mean y2[src]
// CSR: count merged into prep grid; single-pass lookback scan; cursor-free
// fill. PDL hides launch boundaries. Gathers accumulate in packed f32x2
// (add.rn.f32x2: 1 instr = 2 exact fp32 adds) to relieve the issue bound.
// ---------------------------------------------------------------------------

#define MAXN 100000
#define MAXE 1600000

__device__ __half g_x16[(size_t)MAXN * 128];
__device__ __half g_h1[(size_t)MAXN * 128];
__device__ __half g_h2[(size_t)MAXN * 128];
__device__ __half g_agg[(size_t)MAXN * 128];
__device__ __half g_y2[(size_t)MAXN * 64];
__device__ __half g_bt0[128 * 256];            // [n][k]: k<128 Ws, else Wn
__device__ __half g_bt1[128 * 256];
__device__ __half g_bt2c[128 * 128];           // [n][k]: n<64 Wn2, else Ws2
__device__ float g_invdeg[MAXN];
__device__ int   g_degi[MAXN];
__device__ int   g_rowstart[MAXN + 1];
__device__ int   g_colsrc[MAXE];
__device__ int   g_scanstate[1024];            // [0:512) aggregate, [512:1024) flag

// ---------------------------------------------------------------------------
// packed f32x2 helpers (exact: one instruction = two fp32 ops)
// ---------------------------------------------------------------------------
__device__ __forceinline__ void accadd_f32x2(uint64_t& a, uint32_t h2bits) {
    float2 f = __half22float2(*(__half2*)&h2bits);
    asm("{\n\t.reg .b64 t;\n\tmov.b64 t, {%1,%2};\n\tadd.rn.f32x2 %0, %0, t;\n\t}"
        : "+l"(a) : "f"(f.x), "f"(f.y));
}
__device__ __forceinline__ float2 unpack_f32x2(uint64_t a) {
    float2 f;
    asm("mov.b64 {%0,%1}, %2;" : "=f"(f.x), "=f"(f.y) : "l"(a));
    return f;
}

// ---------------------------------------------------------------------------
// merged prep: x->fp16, weights, scanstate zero, degree count (degi pre-zeroed)
// ---------------------------------------------------------------------------
__global__ void prep_all_kernel(const float* __restrict__ x, __half* __restrict__ x16, int n4,
                                const float* __restrict__ Ws0, const float* __restrict__ Wn0,
                                __half* __restrict__ bt0,
                                const float* __restrict__ Ws1, const float* __restrict__ Wn1,
                                __half* __restrict__ bt1,
                                const float* __restrict__ Ws2, const float* __restrict__ Wn2,
                                __half* __restrict__ bt2c,
                                int* __restrict__ scanstate,
                                const int* __restrict__ dst, int* __restrict__ degi, int E,
                                int NXB) {
    int b = blockIdx.x;
    if (b < NXB) {
        int i = b * 256 + threadIdx.x;          // float4 slots
        if (i >= n4) return;
        float4 v = *(const float4*)(x + (size_t)i * 4);
        __half2 h0 = __floats2half2_rn(v.x, v.y);
        __half2 h1 = __floats2half2_rn(v.z, v.w);
        uint2 u;
        u.x = *(uint32_t*)&h0;
        u.y = *(uint32_t*)&h1;
        *(uint2*)(x16 + (size_t)i * 4) = u;
        return;
    }
    b -= NXB;
    if (b < 256) {  // bt0 / bt1 (dual, K=256)
        const float* Ws;
        const float* Wn;
        __half* Bt;
        if (b < 128) { Ws = Ws0; Wn = Wn0; Bt = bt0; }
        else         { Ws = Ws1; Wn = Wn1; Bt = bt1; b -= 128; }
        int i = b * 256 + threadIdx.x;
        int n = i >> 8, k = i & 255;
        float v = (k < 128) ? Ws[k * 128 + n] : Wn[(k - 128) * 128 + n];
        Bt[n * 256 + k] = __float2half_rn(v);
        return;
    }
    b -= 256;
    if (b < 64) {   // bt2c: [128 n][128 k], n<64 -> Wn2, n>=64 -> Ws2
        int i = b * 256 + threadIdx.x;
        int n = i >> 7, k = i & 127;
        float v = (n < 64) ? Wn2[k * 64 + n] : Ws2[k * 64 + (n - 64)];
        bt2c[n * 128 + k] = __float2half_rn(v);
        return;
    }
    b -= 64;
    if (b == 0) {   // zero scanstate (1024 ints = 256 int4)
        *(int4*)(scanstate + (size_t)threadIdx.x * 4) = make_int4(0, 0, 0, 0);
        return;
    }
    b -= 1;
    {   // count_deg
        int i = b * 256 + threadIdx.x;
        if (i < E) atomicAdd(&degi[dst[i]], 1);
    }
}

// ---------------------------------------------------------------------------
// single-pass scan with decoupled lookback
// ---------------------------------------------------------------------------
__global__ void scan_fused_kernel(const int* __restrict__ degi,
                                  int* __restrict__ scanstate,
                                  int* __restrict__ rowstart,
                                  float* __restrict__ invdeg, int N) {
    cudaTriggerProgrammaticLaunchCompletion();
    cudaGridDependencySynchronize();

    __shared__ int s[256];
    __shared__ int red[256];
    const int t = threadIdx.x;
    const int b = blockIdx.x;
    const int i = b * 256 + t;

    int v = (i < N) ? degi[i] : 0;
    s[t] = v;
    __syncthreads();
    for (int off = 1; off < 256; off <<= 1) {
        int u = (t >= off) ? s[t - off] : 0;
        __syncthreads();
        s[t] += u;
        __syncthreads();
    }

    if (t == 0) {
        scanstate[b] = s[255];
        __threadfence();
        *((volatile int*)&scanstate[512 + b]) = 1;
    }

    int partial = 0;
    for (int j = t; j < b; j += 256) {
        while (*((volatile int*)&scanstate[512 + j]) == 0) { }
        partial += *((volatile int*)&scanstate[j]);
    }
    red[t] = partial;
    __syncthreads();
#pragma unroll
    for (int off = 128; off > 0; off >>= 1) {
        if (t < off) red[t] += red[t + off];
        __syncthreads();
    }
    const int blockoff = red[0];

    if (i < N) {
        int excl = s[t] - v + blockoff;
        rowstart[i] = excl;
        invdeg[i] = 1.0f / fmaxf((float)v, 1.0f);
        if (i == N - 1) rowstart[N] = excl + v;
    }
}

// cursor-free fill: degi (post-scan) doubles as down-counter
__global__ void fill_kernel(const int* __restrict__ src,
                            const int* __restrict__ dst,
                            const int* __restrict__ rowstart,
                            int* __restrict__ degi,
                            int* __restrict__ colsrc, int E) {
    cudaTriggerProgrammaticLaunchCompletion();
    int i = blockIdx.x * blockDim.x + threadIdx.x;
    int s = 0, d = 0;
    if (i < E) { s = src[i]; d = dst[i]; }     // inputs: safe pre-sync
    cudaGridDependencySynchronize();
    if (i >= E) return;
    int pos = rowstart[d] + atomicSub(&degi[d], 1) - 1;
    colsrc[pos] = s;
}

// ---------------------------------------------------------------------------
// gather128: 16 lanes per node (uint4 = 8 halves / lane). f32x2 accumulation.
// ---------------------------------------------------------------------------
__device__ __forceinline__ void acc_u4(uint64_t* a, uint4 u) {
    accadd_f32x2(a[0], u.x);
    accadd_f32x2(a[1], u.y);
    accadd_f32x2(a[2], u.z);
    accadd_f32x2(a[3], u.w);
}

__device__ __forceinline__ uint4 pack8_64(const uint64_t* a, float id) {
    float2 f0 = unpack_f32x2(a[0]);
    float2 f1 = unpack_f32x2(a[1]);
    float2 f2 = unpack_f32x2(a[2]);
    float2 f3 = unpack_f32x2(a[3]);
    __half2 o0 = __floats2half2_rn(f0.x * id, f0.y * id);
    __half2 o1 = __floats2half2_rn(f1.x * id, f1.y * id);
    __half2 o2 = __floats2half2_rn(f2.x * id, f2.y * id);
    __half2 o3 = __floats2half2_rn(f3.x * id, f3.y * id);
    uint4 o;
    o.x = *(uint32_t*)&o0; o.y = *(uint32_t*)&o1;
    o.z = *(uint32_t*)&o2; o.w = *(uint32_t*)&o3;
    return o;
}

__global__ void gather_kernel(const __half* __restrict__ h,
                              const int* __restrict__ rowstart,
                              const int* __restrict__ colsrc,
                              const float* __restrict__ invdeg,
                              __half* __restrict__ agg, int N) {
    cudaTriggerProgrammaticLaunchCompletion();
    cudaGridDependencySynchronize();

    int node = (blockIdx.x * blockDim.x + threadIdx.x) >> 4;
    int lane = threadIdx.x & 15;
    if (node >= N) return;
    int beg = rowstart[node];
    int end = rowstart[node + 1];

    const __half* hb = h + lane * 8;
    uint64_t acc[4] = {0ull, 0ull, 0ull, 0ull};

    int j = beg;
    for (; j + 4 <= end; j += 4) {
        int s0 = __ldg(colsrc + j + 0);
        int s1 = __ldg(colsrc + j + 1);
        int s2 = __ldg(colsrc + j + 2);
        int s3 = __ldg(colsrc + j + 3);
        uint4 u0 = *(const uint4*)(hb + (size_t)s0 * 128);
        uint4 u1 = *(const uint4*)(hb + (size_t)s1 * 128);
        uint4 u2 = *(const uint4*)(hb + (size_t)s2 * 128);
        uint4 u3 = *(const uint4*)(hb + (size_t)s3 * 128);
        acc_u4(acc, u0); acc_u4(acc, u1); acc_u4(acc, u2); acc_u4(acc, u3);
    }
    for (; j < end; j++) {
        int s = __ldg(colsrc + j);
        uint4 u = *(const uint4*)(hb + (size_t)s * 128);
        acc_u4(acc, u);
    }
    *(uint4*)(agg + (size_t)node * 128 + lane * 8) = pack8_64(acc, invdeg[node]);
}

// gather64_final: 8 lanes/node over y2; adds p2 (fp32, resident in out) + bias.
__global__ void gather64_final_kernel(const __half* __restrict__ y2,
                                      const int* __restrict__ rowstart,
                                      const int* __restrict__ colsrc,
                                      const float* __restrict__ invdeg,
                                      const float* __restrict__ b2,
                                      float* __restrict__ out, int N) {
    cudaTriggerProgrammaticLaunchCompletion();
    cudaGridDependencySynchronize();

    int node = (blockIdx.x * blockDim.x + threadIdx.x) >> 3;
    int lane = threadIdx.x & 7;
    if (node >= N) return;
    int beg = rowstart[node];
    int end = rowstart[node + 1];

    const __half* hb = y2 + lane * 8;
    uint64_t acc[4] = {0ull, 0ull, 0ull, 0ull};

    int j = beg;
    for (; j + 4 <= end; j += 4) {
        int s0 = __ldg(colsrc + j + 0);
        int s1 = __ldg(colsrc + j + 1);
        int s2 = __ldg(colsrc + j + 2);
        int s3 = __ldg(colsrc + j + 3);
        uint4 u0 = *(const uint4*)(hb + (size_t)s0 * 64);
        uint4 u1 = *(const uint4*)(hb + (size_t)s1 * 64);
        uint4 u2 = *(const uint4*)(hb + (size_t)s2 * 64);
        uint4 u3 = *(const uint4*)(hb + (size_t)s3 * 64);
        acc_u4(acc, u0); acc_u4(acc, u1); acc_u4(acc, u2); acc_u4(acc, u3);
    }
    for (; j < end; j++) {
        int s = __ldg(colsrc + j);
        uint4 u = *(const uint4*)(hb + (size_t)s * 64);
        acc_u4(acc, u);
    }

    float id = invdeg[node];
    float2 a0 = unpack_f32x2(acc[0]);
    float2 a1 = unpack_f32x2(acc[1]);
    float2 a2 = unpack_f32x2(acc[2]);
    float2 a3 = unpack_f32x2(acc[3]);
    size_t base = (size_t)node * 64 + lane * 8;
    float4 p0 = *(const float4*)(out + base);
    float4 p1 = *(const float4*)(out + base + 4);
    float4 bv0 = *(const float4*)(b2 + lane * 8);
    float4 bv1 = *(const float4*)(b2 + lane * 8 + 4);
    float4 o0, o1;
    o0.x = p0.x + bv0.x + a0.x * id;
    o0.y = p0.y + bv0.y + a0.y * id;
    o0.z = p0.z + bv0.z + a1.x * id;
    o0.w = p0.w + bv0.w + a1.y * id;
    o1.x = p1.x + bv1.x + a2.x * id;
    o1.y = p1.y + bv1.y + a2.y * id;
    o1.z = p1.z + bv1.z + a3.x * id;
    o1.w = p1.w + bv1.w + a3.y * id;
    *(float4*)(out + base)     = o0;
    *(float4*)(out + base + 4) = o1;
}

// ---------------------------------------------------------------------------
// fp16 MMA helper: m16n8k16, fp32 accumulate
// ---------------------------------------------------------------------------
__device__ __forceinline__ void mma_f16(float& c0, float& c1, float& c2, float& c3,
                                        uint32_t a0, uint32_t a1, uint32_t a2, uint32_t a3,
                                        uint32_t b0, uint32_t b1) {
    asm volatile(
        "mma.sync.aligned.m16n8k16.row.col.f32.f16.f16.f32 "
        "{%0,%1,%2,%3}, {%4,%5,%6,%7}, {%8,%9}, {%0,%1,%2,%3};\n"
        : "+f"(c0), "+f"(c1), "+f"(c2), "+f"(c3)
        : "r"(a0), "r"(a1), "r"(a2), "r"(a3), "r"(b0), "r"(b1));
}

// ---------------------------------------------------------------------------
// fp16 GEMM. DUAL: out = A1@W1 + A2@W2 (K=256). else K=128.
// SPLIT (BN=128): cols 0-63 -> y2 fp16 (outv), cols 64-127 -> p2 fp32 (out2).
// PDL: weight stage-0 loads issued pre-sync (weights are prep-era data).
// ---------------------------------------------------------------------------
template <int BN, bool DUAL, bool RELU, bool BIAS, bool SPLIT>
__launch_bounds__(256, 2)
__global__ void gemm_f16_kernel(const __half* __restrict__ A1,
                                const __half* __restrict__ A2,
                                const __half* __restrict__ Bt,
                                const float* __restrict__ bias,
                                __half* __restrict__ outv,
                                float* __restrict__ out2, int M) {
    constexpr int KT = 32;
    constexpr int NS = DUAL ? 8 : 4;
    constexpr int LDB = DUAL ? 256 : 128;
    constexpr int ST = 40;
    constexpr int NF = BN / 16;
    constexpr int NBU = BN * 8 / 256;

    __shared__ __align__(16) __half As[2][128 * ST];
    __shared__ __align__(16) __half Bs[2][BN * ST];

    const int tid  = threadIdx.x;
    const int wid  = tid >> 5;
    const int lane = tid & 31;
    const int g    = lane >> 2;
    const int t4   = lane & 3;
    const int warpM = wid & 3;
    const int warpN = wid >> 2;
    const int rowBase = blockIdx.x * 128;

    cudaTriggerProgrammaticLaunchCompletion();

    float acc[2][NF][4];
#pragma unroll
    for (int mf = 0; mf < 2; mf++)
#pragma unroll
        for (int nf = 0; nf < NF; nf++)
#pragma unroll
            for (int r = 0; r < 4; r++) acc[mf][nf][r] = 0.f;

    uint2 ra[4];
    uint2 rb[NBU];

    // ---- pre-sync: stage-0 weight loads (prep-era data, safe) ----
#pragma unroll
    for (int i = 0; i < NBU; i++) {
        int f = tid + i * 256;
        int n = f >> 3, q = f & 7;
        rb[i] = *(const uint2*)(Bt + (size_t)n * LDB + q * 4);
    }

    cudaGridDependencySynchronize();

    // ---- stage-0 A loads + smem stores ----
    {
#pragma unroll
        for (int i = 0; i < 4; i++) {
            int f = tid + i * 256;
            int r = f >> 3, q = f & 7;
            int row = rowBase + r;
            uint2 v = make_uint2(0u, 0u);
            if (row < M) v = *(const uint2*)(A1 + (size_t)row * 128 + q * 4);
            *(uint2*)&As[0][r * ST + q * 4] = v;
        }
#pragma unroll
        for (int i = 0; i < NBU; i++) {
            int f = tid + i * 256;
            int n = f >> 3, q = f & 7;
            *(uint2*)&Bs[0][n * ST + q * 4] = rb[i];
        }
    }
    __syncthreads();

    // ---- main loop ----
#pragma unroll 1
    for (int s = 0; s < NS; s++) {
        const int buf = s & 1;

        if (s + 1 < NS) {
            const __half* A = (DUAL && (s + 1 >= 4)) ? A2 : A1;
            const int k0 = (DUAL ? ((s + 1) & 3) : (s + 1)) * KT;
#pragma unroll
            for (int i = 0; i < 4; i++) {
                int f = tid + i * 256;
                int r = f >> 3, q = f & 7;
                int row = rowBase + r;
                ra[i] = make_uint2(0u, 0u);
                if (row < M) ra[i] = *(const uint2*)(A + (size_t)row * 128 + k0 + q * 4);
            }
            const int kb0 = (s + 1) * KT;
#pragma unroll
            for (int i = 0; i < NBU; i++) {
                int f = tid + i * 256;
                int n = f >> 3, q = f & 7;
                rb[i] = *(const uint2*)(Bt + (size_t)n * LDB + kb0 + q * 4);
            }
        }

#pragma unroll
        for (int k16 = 0; k16 < 2; k16++) {
            const int kb = k16 * 16;
            uint32_t a[2][4];
#pragma unroll
            for (int mf = 0; mf < 2; mf++) {
                int r0 = warpM * 32 + mf * 16 + g;
                const __half* p0 = &As[buf][r0 * ST + kb + 2 * t4];
                const __half* p1 = &As[buf][(r0 + 8) * ST + kb + 2 * t4];
                a[mf][0] = *(const uint32_t*)(p0);
                a[mf][1] = *(const uint32_t*)(p1);
                a[mf][2] = *(const uint32_t*)(p0 + 8);
                a[mf][3] = *(const uint32_t*)(p1 + 8);
            }
#pragma unroll
            for (int nf = 0; nf < NF; nf++) {
                int cb = warpN * (BN / 2) + nf * 8 + g;
                const __half* pb = &Bs[buf][cb * ST + kb + 2 * t4];
                uint32_t b0 = *(const uint32_t*)(pb);
                uint32_t b1 = *(const uint32_t*)(pb + 8);
#pragma unroll
                for (int mf = 0; mf < 2; mf++) {
                    mma_f16(acc[mf][nf][0], acc[mf][nf][1],
                            acc[mf][nf][2], acc[mf][nf][3],
                            a[mf][0], a[mf][1], a[mf][2], a[mf][3], b0, b1);
                }
            }
        }

        if (s + 1 < NS) {
            const int nbuf = buf ^ 1;
#pragma unroll
            for (int i = 0; i < 4; i++) {
                int f = tid + i * 256;
                int r = f >> 3, q = f & 7;
                *(uint2*)&As[nbuf][r * ST + q * 4] = ra[i];
            }
#pragma unroll
            for (int i = 0; i < NBU; i++) {
                int f = tid + i * 256;
                int n = f >> 3, q = f & 7;
                *(uint2*)&Bs[nbuf][n * ST + q * 4] = rb[i];
            }
            __syncthreads();
        }
    }

    // ---- epilogue ----
#pragma unroll
    for (int nf = 0; nf < NF; nf++) {
        int col = warpN * (BN / 2) + nf * 8 + t4 * 2;
        float2 bv = make_float2(0.f, 0.f);
        if (BIAS) bv = *(const float2*)(bias + col);
#pragma unroll
        for (int mf = 0; mf < 2; mf++) {
            int r0 = rowBase + warpM * 32 + mf * 16 + g;
            float2 v0 = make_float2(acc[mf][nf][0] + bv.x, acc[mf][nf][1] + bv.y);
            float2 v1 = make_float2(acc[mf][nf][2] + bv.x, acc[mf][nf][3] + bv.y);
            if (RELU) {
                v0.x = fmaxf(v0.x, 0.f); v0.y = fmaxf(v0.y, 0.f);
                v1.x = fmaxf(v1.x, 0.f); v1.y = fmaxf(v1.y, 0.f);
            }
            if (SPLIT) {
                if (warpN == 0) {
                    if (r0 < M) {
                        __half2 hh = __floats2half2_rn(v0.x, v0.y);
                        *(__half2*)(outv + (size_t)r0 * 64 + col) = hh;
                    }
                    if (r0 + 8 < M) {
                        __half2 hh = __floats2half2_rn(v1.x, v1.y);
                        *(__half2*)(outv + (size_t)(r0 + 8) * 64 + col) = hh;
                    }
                } else {
                    int c2 = col - 64;
                    if (r0 < M)     *(float2*)(out2 + (size_t)r0 * 64 + c2)       = v0;
                    if (r0 + 8 < M) *(float2*)(out2 + (size_t)(r0 + 8) * 64 + c2) = v1;
                }
            } else {
                if (r0 < M) {
                    __half2 hh = __floats2half2_rn(v0.x, v0.y);
                    *(__half2*)(outv + (size_t)r0 * BN + col) = hh;
                }
                if (r0 + 8 < M) {
                    __half2 hh = __floats2half2_rn(v1.x, v1.y);
                    *(__half2*)(outv + (size_t)(r0 + 8) * BN + col) = hh;
                }
            }
        }
    }
}

// ---------------------------------------------------------------------------
// PDL launch helper
// ---------------------------------------------------------------------------
template <typename F, typename... Args>
static inline void launch_pdl(F kernel, int grid, Args... args) {
    cudaLaunchAttribute attr[1];
    attr[0].id = cudaLaunchAttributeProgrammaticStreamSerialization;
    attr[0].val.programmaticStreamSerializationAllowed = 1;
    cudaLaunchConfig_t cfg = {};
    cfg.gridDim = dim3(grid);
    cfg.blockDim = dim3(256);
    cfg.dynamicSmemBytes = 0;
    cfg.stream = 0;
    cfg.attrs = attr;
    cfg.numAttrs = 1;
    cudaLaunchKernelEx(&cfg, kernel, args...);
}

// ---------------------------------------------------------------------------
// launch
// ---------------------------------------------------------------------------
extern "C" void kernel_launch(void* const* d_in, const int* in_sizes, int n_in,
                              void* d_out, int out_size) {
    const float* x   = (const float*)d_in[0];
    const int*   src = (const int*)d_in[1];
    const int*   dst = (const int*)d_in[2];
    const float* Ws0 = (const float*)d_in[3];
    const float* Wn0 = (const float*)d_in[4];
    const float* b0  = (const float*)d_in[5];
    const float* Ws1 = (const float*)d_in[6];
    const float* Wn1 = (const float*)d_in[7];
    const float* b1  = (const float*)d_in[8];
    const float* Ws2 = (const float*)d_in[9];
    const float* Wn2 = (const float*)d_in[10];
    const float* b2  = (const float*)d_in[11];
    float* out = (float*)d_out;

    const int M = in_sizes[0] / 128;   // 100000
    const int E = in_sizes[1];         // 1600000

    __half *x16, *h1, *h2, *agg, *y2, *bt0, *bt1, *bt2c;
    float *invdeg;
    int *degi, *rowstart, *colsrc, *scanstate;
    cudaGetSymbolAddress((void**)&x16, g_x16);
    cudaGetSymbolAddress((void**)&h1,  g_h1);
    cudaGetSymbolAddress((void**)&h2,  g_h2);
    cudaGetSymbolAddress((void**)&agg, g_agg);
    cudaGetSymbolAddress((void**)&y2,  g_y2);
    cudaGetSymbolAddress((void**)&bt0, g_bt0);
    cudaGetSymbolAddress((void**)&bt1, g_bt1);
    cudaGetSymbolAddress((void**)&bt2c, g_bt2c);
    cudaGetSymbolAddress((void**)&invdeg, g_invdeg);
    cudaGetSymbolAddress((void**)&degi, g_degi);
    cudaGetSymbolAddress((void**)&rowstart, g_rowstart);
    cudaGetSymbolAddress((void**)&colsrc, g_colsrc);
    cudaGetSymbolAddress((void**)&scanstate, g_scanstate);

    const int gemmBlocks    = (M + 127) / 128;
    const int edgeBlocks    = (E + 255) / 256;
    const int gather128Blks = (M * 16 + 255) / 256;
    const int gather64Blks  = (M * 8 + 255) / 256;
    const int scanBlocks    = (M + 255) / 256;
    const int NXB           = (M * 32 + 255) / 256;   // x16 float4 blocks

    // ---- zero degi, then merged prep (includes count_deg) ----
    cudaMemsetAsync(degi, 0, (size_t)MAXN * sizeof(int));
    prep_all_kernel<<<NXB + 321 + edgeBlocks, 256>>>(
        x, x16, M * 32,
        Ws0, Wn0, bt0,
        Ws1, Wn1, bt1,
        Ws2, Wn2, bt2c,
        scanstate, dst, degi, E, NXB);

    // ---- CSR: scan + cursor-free fill ----
    launch_pdl(scan_fused_kernel, scanBlocks, (const int*)degi, scanstate,
               rowstart, invdeg, M);
    launch_pdl(fill_kernel, edgeBlocks, src, dst, (const int*)rowstart,
               degi, colsrc, E);

    // ---- layer 0: h1 = relu(x@Ws0 + agg(x)@Wn0 + b0) ----
    launch_pdl(gather_kernel, gather128Blks, (const __half*)x16,
               (const int*)rowstart, (const int*)colsrc,
               (const float*)invdeg, agg, M);
    launch_pdl(gemm_f16_kernel<128, true, true, true, false>, gemmBlocks,
               (const __half*)x16, (const __half*)agg, (const __half*)bt0,
               b0, h1, (float*)nullptr, M);

    // ---- layer 1 ----
    launch_pdl(gather_kernel, gather128Blks, (const __half*)h1,
               (const int*)rowstart, (const int*)colsrc,
               (const float*)invdeg, agg, M);
    launch_pdl(gemm_f16_kernel<128, true, true, true, false>, gemmBlocks,
               (const __half*)h1, (const __half*)agg, (const __half*)bt1,
               b1, h2, (float*)nullptr, M);

    // ---- layer 2: [y2|p2] = h2 @ [Wn2|Ws2]; out = p2 + b2 + mean y2[src] ----
    launch_pdl(gemm_f16_kernel<128, false, false, false, true>, gemmBlocks,
               (const __half*)h2, (const __half*)nullptr, (const __half*)bt2c,
               (const float*)nullptr, y2, out, M);
    launch_pdl(gather64_final_kernel, gather64Blks, (const __half*)y2,
               (const int*)rowstart, (const int*)colsrc,
               (const float*)invdeg, b2, out, M);
}

// round 16
// speedup vs baseline: 1.0473x; 1.0473x over previous
#include <cuda_runtime.h>
#include <cuda_fp16.h>
#include <cstdint>

// ---------------------------------------------------------------------------
// GraphSAGE, 3 layers, mean aggregation, fp16 data / fp32 accumulation.
// Layers 0/1: agg = mean h[src]; h' = relu([h|agg] @ [Ws;Wn] + b)  (dual-A)
// Layer 2:    [y2|p2] = h2 @ [Wn2|Ws2]; out = p2 + b2 + mean y2[src]
// CSR: count merged into prep grid; single-pass lookback scan; cursor-free
// fill (atomicSub on degi). All dependent kernels use PDL to hide launch
// boundaries; GEMM prefetches weight tiles pre-sync.
// (This is the validated R14 configuration — best measured: 236.6 us.)
// ---------------------------------------------------------------------------

#define MAXN 100000
#define MAXE 1600000

__device__ __half g_x16[(size_t)MAXN * 128];
__device__ __half g_h1[(size_t)MAXN * 128];
__device__ __half g_h2[(size_t)MAXN * 128];
__device__ __half g_agg[(size_t)MAXN * 128];
__device__ __half g_y2[(size_t)MAXN * 64];
__device__ __half g_bt0[128 * 256];            // [n][k]: k<128 Ws, else Wn
__device__ __half g_bt1[128 * 256];
__device__ __half g_bt2c[128 * 128];           // [n][k]: n<64 Wn2, else Ws2
__device__ float g_invdeg[MAXN];
__device__ int   g_degi[MAXN];
__device__ int   g_rowstart[MAXN + 1];
__device__ int   g_colsrc[MAXE];
__device__ int   g_scanstate[1024];            // [0:512) aggregate, [512:1024) flag

// ---------------------------------------------------------------------------
// merged prep: x->fp16, weights, scanstate zero, degree count (degi pre-zeroed)
// block ranges: [0, NXB)       -> x16
//               [NXB, +128)    -> bt0
//               [.., +128)     -> bt1
//               [.., +64)      -> bt2c
//               [.., +1)       -> zero scanstate
//               [.., +NEB)     -> count_deg over edges
// ---------------------------------------------------------------------------
__global__ void prep_all_kernel(const float* __restrict__ x, __half* __restrict__ x16, int n4,
                                const float* __restrict__ Ws0, const float* __restrict__ Wn0,
                                __half* __restrict__ bt0,
                                const float* __restrict__ Ws1, const float* __restrict__ Wn1,
                                __half* __restrict__ bt1,
                                const float* __restrict__ Ws2, const float* __restrict__ Wn2,
                                __half* __restrict__ bt2c,
                                int* __restrict__ scanstate,
                                const int* __restrict__ dst, int* __restrict__ degi, int E,
                                int NXB) {
    int b = blockIdx.x;
    if (b < NXB) {
        int i = b * 256 + threadIdx.x;          // float4 slots
        if (i >= n4) return;
        float4 v = *(const float4*)(x + (size_t)i * 4);
        __half2 h0 = __floats2half2_rn(v.x, v.y);
        __half2 h1 = __floats2half2_rn(v.z, v.w);
        uint2 u;
        u.x = *(uint32_t*)&h0;
        u.y = *(uint32_t*)&h1;
        *(uint2*)(x16 + (size_t)i * 4) = u;
        return;
    }
    b -= NXB;
    if (b < 256) {  // bt0 / bt1 (dual, K=256)
        const float* Ws;
        const float* Wn;
        __half* Bt;
        if (b < 128) { Ws = Ws0; Wn = Wn0; Bt = bt0; }
        else         { Ws = Ws1; Wn = Wn1; Bt = bt1; b -= 128; }
        int i = b * 256 + threadIdx.x;
        int n = i >> 8, k = i & 255;
        float v = (k < 128) ? Ws[k * 128 + n] : Wn[(k - 128) * 128 + n];
        Bt[n * 256 + k] = __float2half_rn(v);
        return;
    }
    b -= 256;
    if (b < 64) {   // bt2c: [128 n][128 k], n<64 -> Wn2, n>=64 -> Ws2
        int i = b * 256 + threadIdx.x;
        int n = i >> 7, k = i & 127;
        float v = (n < 64) ? Wn2[k * 64 + n] : Ws2[k * 64 + (n - 64)];
        bt2c[n * 128 + k] = __float2half_rn(v);
        return;
    }
    b -= 64;
    if (b == 0) {   // zero scanstate (1024 ints = 256 int4)
        *(int4*)(scanstate + (size_t)threadIdx.x * 4) = make_int4(0, 0, 0, 0);
        return;
    }
    b -= 1;
    {   // count_deg
        int i = b * 256 + threadIdx.x;
        if (i < E) atomicAdd(&degi[dst[i]], 1);
    }
}

// ---------------------------------------------------------------------------
// single-pass scan with decoupled lookback
// ---------------------------------------------------------------------------
__global__ void scan_fused_kernel(const int* __restrict__ degi,
                                  int* __restrict__ scanstate,
                                  int* __restrict__ rowstart,
                                  float* __restrict__ invdeg, int N) {
    cudaTriggerProgrammaticLaunchCompletion();
    cudaGridDependencySynchronize();

    __shared__ int s[256];
    __shared__ int red[256];
    const int t = threadIdx.x;
    const int b = blockIdx.x;
    const int i = b * 256 + t;

    int v = (i < N) ? degi[i] : 0;
    s[t] = v;
    __syncthreads();
    for (int off = 1; off < 256; off <<= 1) {
        int u = (t >= off) ? s[t - off] : 0;
        __syncthreads();
        s[t] += u;
        __syncthreads();
    }

    if (t == 0) {
        scanstate[b] = s[255];
        __threadfence();
        *((volatile int*)&scanstate[512 + b]) = 1;
    }

    int partial = 0;
    for (int j = t; j < b; j += 256) {
        while (*((volatile int*)&scanstate[512 + j]) == 0) { }
        partial += *((volatile int*)&scanstate[j]);
    }
    red[t] = partial;
    __syncthreads();
#pragma unroll
    for (int off = 128; off > 0; off >>= 1) {
        if (t < off) red[t] += red[t + off];
        __syncthreads();
    }
    const int blockoff = red[0];

    if (i < N) {
        int excl = s[t] - v + blockoff;
        rowstart[i] = excl;
        invdeg[i] = 1.0f / fmaxf((float)v, 1.0f);
        if (i == N - 1) rowstart[N] = excl + v;
    }
}

// cursor-free fill: degi (post-scan) doubles as down-counter
__global__ void fill_kernel(const int* __restrict__ src,
                            const int* __restrict__ dst,
                            const int* __restrict__ rowstart,
                            int* __restrict__ degi,
                            int* __restrict__ colsrc, int E) {
    cudaTriggerProgrammaticLaunchCompletion();
    int i = blockIdx.x * blockDim.x + threadIdx.x;
    int s = 0, d = 0;
    if (i < E) { s = src[i]; d = dst[i]; }     // inputs: safe pre-sync
    cudaGridDependencySynchronize();
    if (i >= E) return;
    int pos = rowstart[d] + atomicSub(&degi[d], 1) - 1;
    colsrc[pos] = s;
}

// ---------------------------------------------------------------------------
// gather helpers
// ---------------------------------------------------------------------------
__device__ __forceinline__ void acc_u4(float* a, uint4 u) {
    float2 p0 = __half22float2(*(__half2*)&u.x);
    float2 p1 = __half22float2(*(__half2*)&u.y);
    float2 p2 = __half22float2(*(__half2*)&u.z);
    float2 p3 = __half22float2(*(__half2*)&u.w);
    a[0] += p0.x; a[1] += p0.y; a[2] += p1.x; a[3] += p1.y;
    a[4] += p2.x; a[5] += p2.y; a[6] += p3.x; a[7] += p3.y;
}

__device__ __forceinline__ uint4 pack8(const float* a, float id) {
    __half2 o0 = __floats2half2_rn(a[0] * id, a[1] * id);
    __half2 o1 = __floats2half2_rn(a[2] * id, a[3] * id);
    __half2 o2 = __floats2half2_rn(a[4] * id, a[5] * id);
    __half2 o3 = __floats2half2_rn(a[6] * id, a[7] * id);
    uint4 o;
    o.x = *(uint32_t*)&o0; o.y = *(uint32_t*)&o1;
    o.z = *(uint32_t*)&o2; o.w = *(uint32_t*)&o3;
    return o;
}

// gather128: 16 lanes per node (uint4 = 8 halves / lane). fp32 accumulation.
__global__ void gather_kernel(const __half* __restrict__ h,
                              const int* __restrict__ rowstart,
                              const int* __restrict__ colsrc,
                              const float* __restrict__ invdeg,
                              __half* __restrict__ agg, int N) {
    cudaTriggerProgrammaticLaunchCompletion();
    cudaGridDependencySynchronize();

    int node = (blockIdx.x * blockDim.x + threadIdx.x) >> 4;
    int lane = threadIdx.x & 15;
    if (node >= N) return;
    int beg = rowstart[node];
    int end = rowstart[node + 1];

    const __half* hb = h + lane * 8;
    float acc[8];
#pragma unroll
    for (int i = 0; i < 8; i++) acc[i] = 0.f;

    int j = beg;
    for (; j + 4 <= end; j += 4) {
        int s0 = __ldg(colsrc + j + 0);
        int s1 = __ldg(colsrc + j + 1);
        int s2 = __ldg(colsrc + j + 2);
        int s3 = __ldg(colsrc + j + 3);
        uint4 u0 = *(const uint4*)(hb + (size_t)s0 * 128);
        uint4 u1 = *(const uint4*)(hb + (size_t)s1 * 128);
        uint4 u2 = *(const uint4*)(hb + (size_t)s2 * 128);
        uint4 u3 = *(const uint4*)(hb + (size_t)s3 * 128);
        acc_u4(acc, u0); acc_u4(acc, u1); acc_u4(acc, u2); acc_u4(acc, u3);
    }
    for (; j < end; j++) {
        int s = __ldg(colsrc + j);
        uint4 u = *(const uint4*)(hb + (size_t)s * 128);
        acc_u4(acc, u);
    }
    *(uint4*)(agg + (size_t)node * 128 + lane * 8) = pack8(acc, invdeg[node]);
}

// gather64_final: 8 lanes/node over y2; adds p2 (fp32, resident in out) + bias.
__global__ void gather64_final_kernel(const __half* __restrict__ y2,
                                      const int* __restrict__ rowstart,
                                      const int* __restrict__ colsrc,
                                      const float* __restrict__ invdeg,
                                      const float* __restrict__ b2,
                                      float* __restrict__ out, int N) {
    cudaTriggerProgrammaticLaunchCompletion();
    cudaGridDependencySynchronize();

    int node = (blockIdx.x * blockDim.x + threadIdx.x) >> 3;
    int lane = threadIdx.x & 7;
    if (node >= N) return;
    int beg = rowstart[node];
    int end = rowstart[node + 1];

    const __half* hb = y2 + lane * 8;
    float acc[8];
#pragma unroll
    for (int i = 0; i < 8; i++) acc[i] = 0.f;

    int j = beg;
    for (; j + 4 <= end; j += 4) {
        int s0 = __ldg(colsrc + j + 0);
        int s1 = __ldg(colsrc + j + 1);
        int s2 = __ldg(colsrc + j + 2);
        int s3 = __ldg(colsrc + j + 3);
        uint4 u0 = *(const uint4*)(hb + (size_t)s0 * 64);
        uint4 u1 = *(const uint4*)(hb + (size_t)s1 * 64);
        uint4 u2 = *(const uint4*)(hb + (size_t)s2 * 64);
        uint4 u3 = *(const uint4*)(hb + (size_t)s3 * 64);
        acc_u4(acc, u0); acc_u4(acc, u1); acc_u4(acc, u2); acc_u4(acc, u3);
    }
    for (; j < end; j++) {
        int s = __ldg(colsrc + j);
        uint4 u = *(const uint4*)(hb + (size_t)s * 64);
        acc_u4(acc, u);
    }

    float id = invdeg[node];
    size_t base = (size_t)node * 64 + lane * 8;
    float4 p0 = *(const float4*)(out + base);
    float4 p1 = *(const float4*)(out + base + 4);
    float4 bv0 = *(const float4*)(b2 + lane * 8);
    float4 bv1 = *(const float4*)(b2 + lane * 8 + 4);
    float4 o0, o1;
    o0.x = p0.x + bv0.x + acc[0] * id;
    o0.y = p0.y + bv0.y + acc[1] * id;
    o0.z = p0.z + bv0.z + acc[2] * id;
    o0.w = p0.w + bv0.w + acc[3] * id;
    o1.x = p1.x + bv1.x + acc[4] * id;
    o1.y = p1.y + bv1.y + acc[5] * id;
    o1.z = p1.z + bv1.z + acc[6] * id;
    o1.w = p1.w + bv1.w + acc[7] * id;
    *(float4*)(out + base)     = o0;
    *(float4*)(out + base + 4) = o1;
}

// ---------------------------------------------------------------------------
// fp16 MMA helper: m16n8k16, fp32 accumulate
// ---------------------------------------------------------------------------
__device__ __forceinline__ void mma_f16(float& c0, float& c1, float& c2, float& c3,
                                        uint32_t a0, uint32_t a1, uint32_t a2, uint32_t a3,
                                        uint32_t b0, uint32_t b1) {
    asm volatile(
        "mma.sync.aligned.m16n8k16.row.col.f32.f16.f16.f32 "
        "{%0,%1,%2,%3}, {%4,%5,%6,%7}, {%8,%9}, {%0,%1,%2,%3};\n"
        : "+f"(c0), "+f"(c1), "+f"(c2), "+f"(c3)
        : "r"(a0), "r"(a1), "r"(a2), "r"(a3), "r"(b0), "r"(b1));
}

// ---------------------------------------------------------------------------
// fp16 GEMM. DUAL: out = A1@W1 + A2@W2 (K=256). else K=128.
// SPLIT (BN=128): cols 0-63 -> y2 fp16 (outv), cols 64-127 -> p2 fp32 (out2).
// PDL: weight stage-0 loads issued pre-sync (weights are prep-era data).
// ---------------------------------------------------------------------------
template <int BN, bool DUAL, bool RELU, bool BIAS, bool SPLIT>
__launch_bounds__(256, 2)
__global__ void gemm_f16_kernel(const __half* __restrict__ A1,
                                const __half* __restrict__ A2,
                                const __half* __restrict__ Bt,
                                const float* __restrict__ bias,
                                __half* __restrict__ outv,
                                float* __restrict__ out2, int M) {
    constexpr int KT = 32;
    constexpr int NS = DUAL ? 8 : 4;
    constexpr int LDB = DUAL ? 256 : 128;
    constexpr int ST = 40;
    constexpr int NF = BN / 16;
    constexpr int NBU = BN * 8 / 256;

    __shared__ __align__(16) __half As[2][128 * ST];
    __shared__ __align__(16) __half Bs[2][BN * ST];

    const int tid  = threadIdx.x;
    const int wid  = tid >> 5;
    const int lane = tid & 31;
    const int g    = lane >> 2;
    const int t4   = lane & 3;
    const int warpM = wid & 3;
    const int warpN = wid >> 2;
    const int rowBase = blockIdx.x * 128;

    cudaTriggerProgrammaticLaunchCompletion();

    float acc[2][NF][4];
#pragma unroll
    for (int mf = 0; mf < 2; mf++)
#pragma unroll
        for (int nf = 0; nf < NF; nf++)
#pragma unroll
            for (int r = 0; r < 4; r++) acc[mf][nf][r] = 0.f;

    uint2 ra[4];
    uint2 rb[NBU];

    // ---- pre-sync: stage-0 weight loads (prep-era data, safe) ----
#pragma unroll
    for (int i = 0; i < NBU; i++) {
        int f = tid + i * 256;
        int n = f >> 3, q = f & 7;
        rb[i] = *(const uint2*)(Bt + (size_t)n * LDB + q * 4);
    }

    cudaGridDependencySynchronize();

    // ---- stage-0 A loads + smem stores ----
    {
#pragma unroll
        for (int i = 0; i < 4; i++) {
            int f = tid + i * 256;
            int r = f >> 3, q = f & 7;
            int row = rowBase + r;
            uint2 v = make_uint2(0u, 0u);
            if (row < M) v = *(const uint2*)(A1 + (size_t)row * 128 + q * 4);
            *(uint2*)&As[0][r * ST + q * 4] = v;
        }
#pragma unroll
        for (int i = 0; i < NBU; i++) {
            int f = tid + i * 256;
            int n = f >> 3, q = f & 7;
            *(uint2*)&Bs[0][n * ST + q * 4] = rb[i];
        }
    }
    __syncthreads();

    // ---- main loop ----
#pragma unroll 1
    for (int s = 0; s < NS; s++) {
        const int buf = s & 1;

        if (s + 1 < NS) {
            const __half* A = (DUAL && (s + 1 >= 4)) ? A2 : A1;
            const int k0 = (DUAL ? ((s + 1) & 3) : (s + 1)) * KT;
#pragma unroll
            for (int i = 0; i < 4; i++) {
                int f = tid + i * 256;
                int r = f >> 3, q = f & 7;
                int row = rowBase + r;
                ra[i] = make_uint2(0u, 0u);
                if (row < M) ra[i] = *(const uint2*)(A + (size_t)row * 128 + k0 + q * 4);
            }
            const int kb0 = (s + 1) * KT;
#pragma unroll
            for (int i = 0; i < NBU; i++) {
                int f = tid + i * 256;
                int n = f >> 3, q = f & 7;
                rb[i] = *(const uint2*)(Bt + (size_t)n * LDB + kb0 + q * 4);
            }
        }

#pragma unroll
        for (int k16 = 0; k16 < 2; k16++) {
            const int kb = k16 * 16;
            uint32_t a[2][4];
#pragma unroll
            for (int mf = 0; mf < 2; mf++) {
                int r0 = warpM * 32 + mf * 16 + g;
                const __half* p0 = &As[buf][r0 * ST + kb + 2 * t4];
                const __half* p1 = &As[buf][(r0 + 8) * ST + kb + 2 * t4];
                a[mf][0] = *(const uint32_t*)(p0);
                a[mf][1] = *(const uint32_t*)(p1);
                a[mf][2] = *(const uint32_t*)(p0 + 8);
                a[mf][3] = *(const uint32_t*)(p1 + 8);
            }
#pragma unroll
            for (int nf = 0; nf < NF; nf++) {
                int cb = warpN * (BN / 2) + nf * 8 + g;
                const __half* pb = &Bs[buf][cb * ST + kb + 2 * t4];
                uint32_t b0 = *(const uint32_t*)(pb);
                uint32_t b1 = *(const uint32_t*)(pb + 8);
#pragma unroll
                for (int mf = 0; mf < 2; mf++) {
                    mma_f16(acc[mf][nf][0], acc[mf][nf][1],
                            acc[mf][nf][2], acc[mf][nf][3],
                            a[mf][0], a[mf][1], a[mf][2], a[mf][3], b0, b1);
                }
            }
        }

        if (s + 1 < NS) {
            const int nbuf = buf ^ 1;
#pragma unroll
            for (int i = 0; i < 4; i++) {
                int f = tid + i * 256;
                int r = f >> 3, q = f & 7;
                *(uint2*)&As[nbuf][r * ST + q * 4] = ra[i];
            }
#pragma unroll
            for (int i = 0; i < NBU; i++) {
                int f = tid + i * 256;
                int n = f >> 3, q = f & 7;
                *(uint2*)&Bs[nbuf][n * ST + q * 4] = rb[i];
            }
            __syncthreads();
        }
    }

    // ---- epilogue ----
#pragma unroll
    for (int nf = 0; nf < NF; nf++) {
        int col = warpN * (BN / 2) + nf * 8 + t4 * 2;
        float2 bv = make_float2(0.f, 0.f);
        if (BIAS) bv = *(const float2*)(bias + col);
#pragma unroll
        for (int mf = 0; mf < 2; mf++) {
            int r0 = rowBase + warpM * 32 + mf * 16 + g;
            float2 v0 = make_float2(acc[mf][nf][0] + bv.x, acc[mf][nf][1] + bv.y);
            float2 v1 = make_float2(acc[mf][nf][2] + bv.x, acc[mf][nf][3] + bv.y);
            if (RELU) {
                v0.x = fmaxf(v0.x, 0.f); v0.y = fmaxf(v0.y, 0.f);
                v1.x = fmaxf(v1.x, 0.f); v1.y = fmaxf(v1.y, 0.f);
            }
            if (SPLIT) {
                if (warpN == 0) {
                    if (r0 < M) {
                        __half2 hh = __floats2half2_rn(v0.x, v0.y);
                        *(__half2*)(outv + (size_t)r0 * 64 + col) = hh;
                    }
                    if (r0 + 8 < M) {
                        __half2 hh = __floats2half2_rn(v1.x, v1.y);
                        *(__half2*)(outv + (size_t)(r0 + 8) * 64 + col) = hh;
                    }
                } else {
                    int c2 = col - 64;
                    if (r0 < M)     *(float2*)(out2 + (size_t)r0 * 64 + c2)       = v0;
                    if (r0 + 8 < M) *(float2*)(out2 + (size_t)(r0 + 8) * 64 + c2) = v1;
                }
            } else {
                if (r0 < M) {
                    __half2 hh = __floats2half2_rn(v0.x, v0.y);
                    *(__half2*)(outv + (size_t)r0 * BN + col) = hh;
                }
                if (r0 + 8 < M) {
                    __half2 hh = __floats2half2_rn(v1.x, v1.y);
                    *(__half2*)(outv + (size_t)(r0 + 8) * BN + col) = hh;
                }
            }
        }
    }
}

// ---------------------------------------------------------------------------
// PDL launch helper
// ---------------------------------------------------------------------------
template <typename F, typename... Args>
static inline void launch_pdl(F kernel, int grid, Args... args) {
    cudaLaunchAttribute attr[1];
    attr[0].id = cudaLaunchAttributeProgrammaticStreamSerialization;
    attr[0].val.programmaticStreamSerializationAllowed = 1;
    cudaLaunchConfig_t cfg = {};
    cfg.gridDim = dim3(grid);
    cfg.blockDim = dim3(256);
    cfg.dynamicSmemBytes = 0;
    cfg.stream = 0;
    cfg.attrs = attr;
    cfg.numAttrs = 1;
    cudaLaunchKernelEx(&cfg, kernel, args...);
}

// ---------------------------------------------------------------------------
// launch
// ---------------------------------------------------------------------------
extern "C" void kernel_launch(void* const* d_in, const int* in_sizes, int n_in,
                              void* d_out, int out_size) {
    const float* x   = (const float*)d_in[0];
    const int*   src = (const int*)d_in[1];
    const int*   dst = (const int*)d_in[2];
    const float* Ws0 = (const float*)d_in[3];
    const float* Wn0 = (const float*)d_in[4];
    const float* b0  = (const float*)d_in[5];
    const float* Ws1 = (const float*)d_in[6];
    const float* Wn1 = (const float*)d_in[7];
    const float* b1  = (const float*)d_in[8];
    const float* Ws2 = (const float*)d_in[9];
    const float* Wn2 = (const float*)d_in[10];
    const float* b2  = (const float*)d_in[11];
    float* out = (float*)d_out;

    const int M = in_sizes[0] / 128;   // 100000
    const int E = in_sizes[1];         // 1600000

    __half *x16, *h1, *h2, *agg, *y2, *bt0, *bt1, *bt2c;
    float *invdeg;
    int *degi, *rowstart, *colsrc, *scanstate;
    cudaGetSymbolAddress((void**)&x16, g_x16);
    cudaGetSymbolAddress((void**)&h1,  g_h1);
    cudaGetSymbolAddress((void**)&h2,  g_h2);
    cudaGetSymbolAddress((void**)&agg, g_agg);
    cudaGetSymbolAddress((void**)&y2,  g_y2);
    cudaGetSymbolAddress((void**)&bt0, g_bt0);
    cudaGetSymbolAddress((void**)&bt1, g_bt1);
    cudaGetSymbolAddress((void**)&bt2c, g_bt2c);
    cudaGetSymbolAddress((void**)&invdeg, g_invdeg);
    cudaGetSymbolAddress((void**)&degi, g_degi);
    cudaGetSymbolAddress((void**)&rowstart, g_rowstart);
    cudaGetSymbolAddress((void**)&colsrc, g_colsrc);
    cudaGetSymbolAddress((void**)&scanstate, g_scanstate);

    const int gemmBlocks    = (M + 127) / 128;
    const int edgeBlocks    = (E + 255) / 256;
    const int gather128Blks = (M * 16 + 255) / 256;
    const int gather64Blks  = (M * 8 + 255) / 256;
    const int scanBlocks    = (M + 255) / 256;
    const int NXB           = (M * 32 + 255) / 256;   // x16 float4 blocks

    // ---- zero degi, then merged prep (includes count_deg) ----
    cudaMemsetAsync(degi, 0, (size_t)MAXN * sizeof(int));
    prep_all_kernel<<<NXB + 321 + edgeBlocks, 256>>>(
        x, x16, M * 32,
        Ws0, Wn0, bt0,
        Ws1, Wn1, bt1,
        Ws2, Wn2, bt2c,
        scanstate, dst, degi, E, NXB);

    // ---- CSR: scan + cursor-free fill ----
    launch_pdl(scan_fused_kernel, scanBlocks, (const int*)degi, scanstate,
               rowstart, invdeg, M);
    launch_pdl(fill_kernel, edgeBlocks, src, dst, (const int*)rowstart,
               degi, colsrc, E);

    // ---- layer 0: h1 = relu(x@Ws0 + agg(x)@Wn0 + b0) ----
    launch_pdl(gather_kernel, gather128Blks, (const __half*)x16,
               (const int*)rowstart, (const int*)colsrc,
               (const float*)invdeg, agg, M);
    launch_pdl(gemm_f16_kernel<128, true, true, true, false>, gemmBlocks,
               (const __half*)x16, (const __half*)agg, (const __half*)bt0,
               b0, h1, (float*)nullptr, M);

    // ---- layer 1 ----
    launch_pdl(gather_kernel, gather128Blks, (const __half*)h1,
               (const int*)rowstart, (const int*)colsrc,
               (const float*)invdeg, agg, M);
    launch_pdl(gemm_f16_kernel<128, true, true, true, false>, gemmBlocks,
               (const __half*)h1, (const __half*)agg, (const __half*)bt1,
               b1, h2, (float*)nullptr, M);

    // ---- layer 2: [y2|p2] = h2 @ [Wn2|Ws2]; out = p2 + b2 + mean y2[src] ----
    launch_pdl(gemm_f16_kernel<128, false, false, false, true>, gemmBlocks,
               (const __half*)h2, (const __half*)nullptr, (const __half*)bt2c,
               (const float*)nullptr, y2, out, M);
    launch_pdl(gather64_final_kernel, gather64Blks, (const __half*)y2,
               (const int*)rowstart, (const int*)colsrc,
               (const float*)invdeg, b2, out, M);
}

// round 17
// speedup vs baseline: 1.0773x; 1.0287x over previous
#include <cuda_runtime.h>
#include <cuda_fp16.h>
#include <cstdint>

// ---------------------------------------------------------------------------
// GraphSAGE, 3 layers, mean aggregation, fp16 data / fp32 accumulation.
// Layers 0/1: agg = mean h[src]; h' = relu([h|agg] @ [Ws;Wn] + b)  (dual-A)
// Layer 2:    [y2|p2] = h2 @ [Wn2|Ws2]; out = p2 + b2 + mean y2[src]
// CSR: count merged into prep grid; single-pass lookback scan; cursor-free
// fill. PDL hides launch boundaries. Gathers pre-add edge PAIRS in fp16
// (HADD2) before fp32 accumulation: 37% fewer fma-pipe ops, no extra regs.
// ---------------------------------------------------------------------------

#define MAXN 100000
#define MAXE 1600000

__device__ __half g_x16[(size_t)MAXN * 128];
__device__ __half g_h1[(size_t)MAXN * 128];
__device__ __half g_h2[(size_t)MAXN * 128];
__device__ __half g_agg[(size_t)MAXN * 128];
__device__ __half g_y2[(size_t)MAXN * 64];
__device__ __half g_bt0[128 * 256];            // [n][k]: k<128 Ws, else Wn
__device__ __half g_bt1[128 * 256];
__device__ __half g_bt2c[128 * 128];           // [n][k]: n<64 Wn2, else Ws2
__device__ float g_invdeg[MAXN];
__device__ int   g_degi[MAXN];
__device__ int   g_rowstart[MAXN + 1];
__device__ int   g_colsrc[MAXE];
__device__ int   g_scanstate[1024];            // [0:512) aggregate, [512:1024) flag

// ---------------------------------------------------------------------------
// merged prep: x->fp16, weights, scanstate zero, degree count (degi pre-zeroed)
// ---------------------------------------------------------------------------
__global__ void prep_all_kernel(const float* __restrict__ x, __half* __restrict__ x16, int n4,
                                const float* __restrict__ Ws0, const float* __restrict__ Wn0,
                                __half* __restrict__ bt0,
                                const float* __restrict__ Ws1, const float* __restrict__ Wn1,
                                __half* __restrict__ bt1,
                                const float* __restrict__ Ws2, const float* __restrict__ Wn2,
                                __half* __restrict__ bt2c,
                                int* __restrict__ scanstate,
                                const int* __restrict__ dst, int* __restrict__ degi, int E,
                                int NXB) {
    int b = blockIdx.x;
    if (b < NXB) {
        int i = b * 256 + threadIdx.x;          // float4 slots
        if (i >= n4) return;
        float4 v = *(const float4*)(x + (size_t)i * 4);
        __half2 h0 = __floats2half2_rn(v.x, v.y);
        __half2 h1 = __floats2half2_rn(v.z, v.w);
        uint2 u;
        u.x = *(uint32_t*)&h0;
        u.y = *(uint32_t*)&h1;
        *(uint2*)(x16 + (size_t)i * 4) = u;
        return;
    }
    b -= NXB;
    if (b < 256) {  // bt0 / bt1 (dual, K=256)
        const float* Ws;
        const float* Wn;
        __half* Bt;
        if (b < 128) { Ws = Ws0; Wn = Wn0; Bt = bt0; }
        else         { Ws = Ws1; Wn = Wn1; Bt = bt1; b -= 128; }
        int i = b * 256 + threadIdx.x;
        int n = i >> 8, k = i & 255;
        float v = (k < 128) ? Ws[k * 128 + n] : Wn[(k - 128) * 128 + n];
        Bt[n * 256 + k] = __float2half_rn(v);
        return;
    }
    b -= 256;
    if (b < 64) {   // bt2c: [128 n][128 k], n<64 -> Wn2, n>=64 -> Ws2
        int i = b * 256 + threadIdx.x;
        int n = i >> 7, k = i & 127;
        float v = (n < 64) ? Wn2[k * 64 + n] : Ws2[k * 64 + (n - 64)];
        bt2c[n * 128 + k] = __float2half_rn(v);
        return;
    }
    b -= 64;
    if (b == 0) {   // zero scanstate (1024 ints = 256 int4)
        *(int4*)(scanstate + (size_t)threadIdx.x * 4) = make_int4(0, 0, 0, 0);
        return;
    }
    b -= 1;
    {   // count_deg
        int i = b * 256 + threadIdx.x;
        if (i < E) atomicAdd(&degi[dst[i]], 1);
    }
}

// ---------------------------------------------------------------------------
// single-pass scan with decoupled lookback
// ---------------------------------------------------------------------------
__global__ void scan_fused_kernel(const int* __restrict__ degi,
                                  int* __restrict__ scanstate,
                                  int* __restrict__ rowstart,
                                  float* __restrict__ invdeg, int N) {
    cudaTriggerProgrammaticLaunchCompletion();
    cudaGridDependencySynchronize();

    __shared__ int s[256];
    __shared__ int red[256];
    const int t = threadIdx.x;
    const int b = blockIdx.x;
    const int i = b * 256 + t;

    int v = (i < N) ? degi[i] : 0;
    s[t] = v;
    __syncthreads();
    for (int off = 1; off < 256; off <<= 1) {
        int u = (t >= off) ? s[t - off] : 0;
        __syncthreads();
        s[t] += u;
        __syncthreads();
    }

    if (t == 0) {
        scanstate[b] = s[255];
        __threadfence();
        *((volatile int*)&scanstate[512 + b]) = 1;
    }

    int partial = 0;
    for (int j = t; j < b; j += 256) {
        while (*((volatile int*)&scanstate[512 + j]) == 0) { }
        partial += *((volatile int*)&scanstate[j]);
    }
    red[t] = partial;
    __syncthreads();
#pragma unroll
    for (int off = 128; off > 0; off >>= 1) {
        if (t < off) red[t] += red[t + off];
        __syncthreads();
    }
    const int blockoff = red[0];

    if (i < N) {
        int excl = s[t] - v + blockoff;
        rowstart[i] = excl;
        invdeg[i] = 1.0f / fmaxf((float)v, 1.0f);
        if (i == N - 1) rowstart[N] = excl + v;
    }
}

// cursor-free fill: degi (post-scan) doubles as down-counter
__global__ void fill_kernel(const int* __restrict__ src,
                            const int* __restrict__ dst,
                            const int* __restrict__ rowstart,
                            int* __restrict__ degi,
                            int* __restrict__ colsrc, int E) {
    cudaTriggerProgrammaticLaunchCompletion();
    int i = blockIdx.x * blockDim.x + threadIdx.x;
    int s = 0, d = 0;
    if (i < E) { s = src[i]; d = dst[i]; }     // inputs: safe pre-sync
    cudaGridDependencySynchronize();
    if (i >= E) return;
    int pos = rowstart[d] + atomicSub(&degi[d], 1) - 1;
    colsrc[pos] = s;
}

// ---------------------------------------------------------------------------
// gather helpers
// ---------------------------------------------------------------------------
__device__ __forceinline__ void acc_u4(float* a, uint4 u) {
    float2 p0 = __half22float2(*(__half2*)&u.x);
    float2 p1 = __half22float2(*(__half2*)&u.y);
    float2 p2 = __half22float2(*(__half2*)&u.z);
    float2 p3 = __half22float2(*(__half2*)&u.w);
    a[0] += p0.x; a[1] += p0.y; a[2] += p1.x; a[3] += p1.y;
    a[4] += p2.x; a[5] += p2.y; a[6] += p3.x; a[7] += p3.y;
}

// pairwise fp16 add of two rows (one HADD2 per half2 word)
__device__ __forceinline__ uint4 hadd2_u4(uint4 a, uint4 b) {
    uint4 r;
    *(__half2*)&r.x = __hadd2(*(const __half2*)&a.x, *(const __half2*)&b.x);
    *(__half2*)&r.y = __hadd2(*(const __half2*)&a.y, *(const __half2*)&b.y);
    *(__half2*)&r.z = __hadd2(*(const __half2*)&a.z, *(const __half2*)&b.z);
    *(__half2*)&r.w = __hadd2(*(const __half2*)&a.w, *(const __half2*)&b.w);
    return r;
}

__device__ __forceinline__ uint4 pack8(const float* a, float id) {
    __half2 o0 = __floats2half2_rn(a[0] * id, a[1] * id);
    __half2 o1 = __floats2half2_rn(a[2] * id, a[3] * id);
    __half2 o2 = __floats2half2_rn(a[4] * id, a[5] * id);
    __half2 o3 = __floats2half2_rn(a[6] * id, a[7] * id);
    uint4 o;
    o.x = *(uint32_t*)&o0; o.y = *(uint32_t*)&o1;
    o.z = *(uint32_t*)&o2; o.w = *(uint32_t*)&o3;
    return o;
}

// gather128: 16 lanes per node (uint4 = 8 halves / lane). Pairwise fp16
// pre-add, fp32 accumulation.
__global__ void gather_kernel(const __half* __restrict__ h,
                              const int* __restrict__ rowstart,
                              const int* __restrict__ colsrc,
                              const float* __restrict__ invdeg,
                              __half* __restrict__ agg, int N) {
    cudaTriggerProgrammaticLaunchCompletion();
    cudaGridDependencySynchronize();

    int node = (blockIdx.x * blockDim.x + threadIdx.x) >> 4;
    int lane = threadIdx.x & 15;
    if (node >= N) return;
    int beg = rowstart[node];
    int end = rowstart[node + 1];

    const __half* hb = h + lane * 8;
    float acc[8];
#pragma unroll
    for (int i = 0; i < 8; i++) acc[i] = 0.f;

    int j = beg;
    for (; j + 4 <= end; j += 4) {
        int s0 = __ldg(colsrc + j + 0);
        int s1 = __ldg(colsrc + j + 1);
        int s2 = __ldg(colsrc + j + 2);
        int s3 = __ldg(colsrc + j + 3);
        uint4 u0 = *(const uint4*)(hb + (size_t)s0 * 128);
        uint4 u1 = *(const uint4*)(hb + (size_t)s1 * 128);
        uint4 u2 = *(const uint4*)(hb + (size_t)s2 * 128);
        uint4 u3 = *(const uint4*)(hb + (size_t)s3 * 128);
        acc_u4(acc, hadd2_u4(u0, u1));
        acc_u4(acc, hadd2_u4(u2, u3));
    }
    for (; j + 2 <= end; j += 2) {
        int s0 = __ldg(colsrc + j + 0);
        int s1 = __ldg(colsrc + j + 1);
        uint4 u0 = *(const uint4*)(hb + (size_t)s0 * 128);
        uint4 u1 = *(const uint4*)(hb + (size_t)s1 * 128);
        acc_u4(acc, hadd2_u4(u0, u1));
    }
    if (j < end) {
        int s = __ldg(colsrc + j);
        uint4 u = *(const uint4*)(hb + (size_t)s * 128);
        acc_u4(acc, u);
    }
    *(uint4*)(agg + (size_t)node * 128 + lane * 8) = pack8(acc, invdeg[node]);
}

// gather64_final: 8 lanes/node over y2; adds p2 (fp32, resident in out) + bias.
__global__ void gather64_final_kernel(const __half* __restrict__ y2,
                                      const int* __restrict__ rowstart,
                                      const int* __restrict__ colsrc,
                                      const float* __restrict__ invdeg,
                                      const float* __restrict__ b2,
                                      float* __restrict__ out, int N) {
    cudaTriggerProgrammaticLaunchCompletion();
    cudaGridDependencySynchronize();

    int node = (blockIdx.x * blockDim.x + threadIdx.x) >> 3;
    int lane = threadIdx.x & 7;
    if (node >= N) return;
    int beg = rowstart[node];
    int end = rowstart[node + 1];

    const __half* hb = y2 + lane * 8;
    float acc[8];
#pragma unroll
    for (int i = 0; i < 8; i++) acc[i] = 0.f;

    int j = beg;
    for (; j + 4 <= end; j += 4) {
        int s0 = __ldg(colsrc + j + 0);
        int s1 = __ldg(colsrc + j + 1);
        int s2 = __ldg(colsrc + j + 2);
        int s3 = __ldg(colsrc + j + 3);
        uint4 u0 = *(const uint4*)(hb + (size_t)s0 * 64);
        uint4 u1 = *(const uint4*)(hb + (size_t)s1 * 64);
        uint4 u2 = *(const uint4*)(hb + (size_t)s2 * 64);
        uint4 u3 = *(const uint4*)(hb + (size_t)s3 * 64);
        acc_u4(acc, hadd2_u4(u0, u1));
        acc_u4(acc, hadd2_u4(u2, u3));
    }
    for (; j + 2 <= end; j += 2) {
        int s0 = __ldg(colsrc + j + 0);
        int s1 = __ldg(colsrc + j + 1);
        uint4 u0 = *(const uint4*)(hb + (size_t)s0 * 64);
        uint4 u1 = *(const uint4*)(hb + (size_t)s1 * 64);
        acc_u4(acc, hadd2_u4(u0, u1));
    }
    if (j < end) {
        int s = __ldg(colsrc + j);
        uint4 u = *(const uint4*)(hb + (size_t)s * 64);
        acc_u4(acc, u);
    }

    float id = invdeg[node];
    size_t base = (size_t)node * 64 + lane * 8;
    float4 p0 = *(const float4*)(out + base);
    float4 p1 = *(const float4*)(out + base + 4);
    float4 bv0 = *(const float4*)(b2 + lane * 8);
    float4 bv1 = *(const float4*)(b2 + lane * 8 + 4);
    float4 o0, o1;
    o0.x = p0.x + bv0.x + acc[0] * id;
    o0.y = p0.y + bv0.y + acc[1] * id;
    o0.z = p0.z + bv0.z + acc[2] * id;
    o0.w = p0.w + bv0.w + acc[3] * id;
    o1.x = p1.x + bv1.x + acc[4] * id;
    o1.y = p1.y + bv1.y + acc[5] * id;
    o1.z = p1.z + bv1.z + acc[6] * id;
    o1.w = p1.w + bv1.w + acc[7] * id;
    *(float4*)(out + base)     = o0;
    *(float4*)(out + base + 4) = o1;
}

// ---------------------------------------------------------------------------
// fp16 MMA helper: m16n8k16, fp32 accumulate
// ---------------------------------------------------------------------------
__device__ __forceinline__ void mma_f16(float& c0, float& c1, float& c2, float& c3,
                                        uint32_t a0, uint32_t a1, uint32_t a2, uint32_t a3,
                                        uint32_t b0, uint32_t b1) {
    asm volatile(
        "mma.sync.aligned.m16n8k16.row.col.f32.f16.f16.f32 "
        "{%0,%1,%2,%3}, {%4,%5,%6,%7}, {%8,%9}, {%0,%1,%2,%3};\n"
        : "+f"(c0), "+f"(c1), "+f"(c2), "+f"(c3)
        : "r"(a0), "r"(a1), "r"(a2), "r"(a3), "r"(b0), "r"(b1));
}

// ---------------------------------------------------------------------------
// fp16 GEMM. DUAL: out = A1@W1 + A2@W2 (K=256). else K=128.
// SPLIT (BN=128): cols 0-63 -> y2 fp16 (outv), cols 64-127 -> p2 fp32 (out2).
// PDL: weight stage-0 loads issued pre-sync (weights are prep-era data).
// ---------------------------------------------------------------------------
template <int BN, bool DUAL, bool RELU, bool BIAS, bool SPLIT>
__launch_bounds__(256, 2)
__global__ void gemm_f16_kernel(const __half* __restrict__ A1,
                                const __half* __restrict__ A2,
                                const __half* __restrict__ Bt,
                                const float* __restrict__ bias,
                                __half* __restrict__ outv,
                                float* __restrict__ out2, int M) {
    constexpr int KT = 32;
    constexpr int NS = DUAL ? 8 : 4;
    constexpr int LDB = DUAL ? 256 : 128;
    constexpr int ST = 40;
    constexpr int NF = BN / 16;
    constexpr int NBU = BN * 8 / 256;

    __shared__ __align__(16) __half As[2][128 * ST];
    __shared__ __align__(16) __half Bs[2][BN * ST];

    const int tid  = threadIdx.x;
    const int wid  = tid >> 5;
    const int lane = tid & 31;
    const int g    = lane >> 2;
    const int t4   = lane & 3;
    const int warpM = wid & 3;
    const int warpN = wid >> 2;
    const int rowBase = blockIdx.x * 128;

    cudaTriggerProgrammaticLaunchCompletion();

    float acc[2][NF][4];
#pragma unroll
    for (int mf = 0; mf < 2; mf++)
#pragma unroll
        for (int nf = 0; nf < NF; nf++)
#pragma unroll
            for (int r = 0; r < 4; r++) acc[mf][nf][r] = 0.f;

    uint2 ra[4];
    uint2 rb[NBU];

    // ---- pre-sync: stage-0 weight loads (prep-era data, safe) ----
#pragma unroll
    for (int i = 0; i < NBU; i++) {
        int f = tid + i * 256;
        int n = f >> 3, q = f & 7;
        rb[i] = *(const uint2*)(Bt + (size_t)n * LDB + q * 4);
    }

    cudaGridDependencySynchronize();

    // ---- stage-0 A loads + smem stores ----
    {
#pragma unroll
        for (int i = 0; i < 4; i++) {
            int f = tid + i * 256;
            int r = f >> 3, q = f & 7;
            int row = rowBase + r;
            uint2 v = make_uint2(0u, 0u);
            if (row < M) v = *(const uint2*)(A1 + (size_t)row * 128 + q * 4);
            *(uint2*)&As[0][r * ST + q * 4] = v;
        }
#pragma unroll
        for (int i = 0; i < NBU; i++) {
            int f = tid + i * 256;
            int n = f >> 3, q = f & 7;
            *(uint2*)&Bs[0][n * ST + q * 4] = rb[i];
        }
    }
    __syncthreads();

    // ---- main loop ----
#pragma unroll 1
    for (int s = 0; s < NS; s++) {
        const int buf = s & 1;

        if (s + 1 < NS) {
            const __half* A = (DUAL && (s + 1 >= 4)) ? A2 : A1;
            const int k0 = (DUAL ? ((s + 1) & 3) : (s + 1)) * KT;
#pragma unroll
            for (int i = 0; i < 4; i++) {
                int f = tid + i * 256;
                int r = f >> 3, q = f & 7;
                int row = rowBase + r;
                ra[i] = make_uint2(0u, 0u);
                if (row < M) ra[i] = *(const uint2*)(A + (size_t)row * 128 + k0 + q * 4);
            }
            const int kb0 = (s + 1) * KT;
#pragma unroll
            for (int i = 0; i < NBU; i++) {
                int f = tid + i * 256;
                int n = f >> 3, q = f & 7;
                rb[i] = *(const uint2*)(Bt + (size_t)n * LDB + kb0 + q * 4);
            }
        }

#pragma unroll
        for (int k16 = 0; k16 < 2; k16++) {
            const int kb = k16 * 16;
            uint32_t a[2][4];
#pragma unroll
            for (int mf = 0; mf < 2; mf++) {
                int r0 = warpM * 32 + mf * 16 + g;
                const __half* p0 = &As[buf][r0 * ST + kb + 2 * t4];
                const __half* p1 = &As[buf][(r0 + 8) * ST + kb + 2 * t4];
                a[mf][0] = *(const uint32_t*)(p0);
                a[mf][1] = *(const uint32_t*)(p1);
                a[mf][2] = *(const uint32_t*)(p0 + 8);
                a[mf][3] = *(const uint32_t*)(p1 + 8);
            }
#pragma unroll
            for (int nf = 0; nf < NF; nf++) {
                int cb = warpN * (BN / 2) + nf * 8 + g;
                const __half* pb = &Bs[buf][cb * ST + kb + 2 * t4];
                uint32_t b0 = *(const uint32_t*)(pb);
                uint32_t b1 = *(const uint32_t*)(pb + 8);
#pragma unroll
                for (int mf = 0; mf < 2; mf++) {
                    mma_f16(acc[mf][nf][0], acc[mf][nf][1],
                            acc[mf][nf][2], acc[mf][nf][3],
                            a[mf][0], a[mf][1], a[mf][2], a[mf][3], b0, b1);
                }
            }
        }

        if (s + 1 < NS) {
            const int nbuf = buf ^ 1;
#pragma unroll
            for (int i = 0; i < 4; i++) {
                int f = tid + i * 256;
                int r = f >> 3, q = f & 7;
                *(uint2*)&As[nbuf][r * ST + q * 4] = ra[i];
            }
#pragma unroll
            for (int i = 0; i < NBU; i++) {
                int f = tid + i * 256;
                int n = f >> 3, q = f & 7;
                *(uint2*)&Bs[nbuf][n * ST + q * 4] = rb[i];
            }
            __syncthreads();
        }
    }

    // ---- epilogue ----
#pragma unroll
    for (int nf = 0; nf < NF; nf++) {
        int col = warpN * (BN / 2) + nf * 8 + t4 * 2;
        float2 bv = make_float2(0.f, 0.f);
        if (BIAS) bv = *(const float2*)(bias + col);
#pragma unroll
        for (int mf = 0; mf < 2; mf++) {
            int r0 = rowBase + warpM * 32 + mf * 16 + g;
            float2 v0 = make_float2(acc[mf][nf][0] + bv.x, acc[mf][nf][1] + bv.y);
            float2 v1 = make_float2(acc[mf][nf][2] + bv.x, acc[mf][nf][3] + bv.y);
            if (RELU) {
                v0.x = fmaxf(v0.x, 0.f); v0.y = fmaxf(v0.y, 0.f);
                v1.x = fmaxf(v1.x, 0.f); v1.y = fmaxf(v1.y, 0.f);
            }
            if (SPLIT) {
                if (warpN == 0) {
                    if (r0 < M) {
                        __half2 hh = __floats2half2_rn(v0.x, v0.y);
                        *(__half2*)(outv + (size_t)r0 * 64 + col) = hh;
                    }
                    if (r0 + 8 < M) {
                        __half2 hh = __floats2half2_rn(v1.x, v1.y);
                        *(__half2*)(outv + (size_t)(r0 + 8) * 64 + col) = hh;
                    }
                } else {
                    int c2 = col - 64;
                    if (r0 < M)     *(float2*)(out2 + (size_t)r0 * 64 + c2)       = v0;
                    if (r0 + 8 < M) *(float2*)(out2 + (size_t)(r0 + 8) * 64 + c2) = v1;
                }
            } else {
                if (r0 < M) {
                    __half2 hh = __floats2half2_rn(v0.x, v0.y);
                    *(__half2*)(outv + (size_t)r0 * BN + col) = hh;
                }
                if (r0 + 8 < M) {
                    __half2 hh = __floats2half2_rn(v1.x, v1.y);
                    *(__half2*)(outv + (size_t)(r0 + 8) * BN + col) = hh;
                }
            }
        }
    }
}

// ---------------------------------------------------------------------------
// PDL launch helper
// ---------------------------------------------------------------------------
template <typename F, typename... Args>
static inline void launch_pdl(F kernel, int grid, Args... args) {
    cudaLaunchAttribute attr[1];
    attr[0].id = cudaLaunchAttributeProgrammaticStreamSerialization;
    attr[0].val.programmaticStreamSerializationAllowed = 1;
    cudaLaunchConfig_t cfg = {};
    cfg.gridDim = dim3(grid);
    cfg.blockDim = dim3(256);
    cfg.dynamicSmemBytes = 0;
    cfg.stream = 0;
    cfg.attrs = attr;
    cfg.numAttrs = 1;
    cudaLaunchKernelEx(&cfg, kernel, args...);
}

// ---------------------------------------------------------------------------
// launch
// ---------------------------------------------------------------------------
extern "C" void kernel_launch(void* const* d_in, const int* in_sizes, int n_in,
                              void* d_out, int out_size) {
    const float* x   = (const float*)d_in[0];
    const int*   src = (const int*)d_in[1];
    const int*   dst = (const int*)d_in[2];
    const float* Ws0 = (const float*)d_in[3];
    const float* Wn0 = (const float*)d_in[4];
    const float* b0  = (const float*)d_in[5];
    const float* Ws1 = (const float*)d_in[6];
    const float* Wn1 = (const float*)d_in[7];
    const float* b1  = (const float*)d_in[8];
    const float* Ws2 = (const float*)d_in[9];
    const float* Wn2 = (const float*)d_in[10];
    const float* b2  = (const float*)d_in[11];
    float* out = (float*)d_out;

    const int M = in_sizes[0] / 128;   // 100000
    const int E = in_sizes[1];         // 1600000

    __half *x16, *h1, *h2, *agg, *y2, *bt0, *bt1, *bt2c;
    float *invdeg;
    int *degi, *rowstart, *colsrc, *scanstate;
    cudaGetSymbolAddress((void**)&x16, g_x16);
    cudaGetSymbolAddress((void**)&h1,  g_h1);
    cudaGetSymbolAddress((void**)&h2,  g_h2);
    cudaGetSymbolAddress((void**)&agg, g_agg);
    cudaGetSymbolAddress((void**)&y2,  g_y2);
    cudaGetSymbolAddress((void**)&bt0, g_bt0);
    cudaGetSymbolAddress((void**)&bt1, g_bt1);
    cudaGetSymbolAddress((void**)&bt2c, g_bt2c);
    cudaGetSymbolAddress((void**)&invdeg, g_invdeg);
    cudaGetSymbolAddress((void**)&degi, g_degi);
    cudaGetSymbolAddress((void**)&rowstart, g_rowstart);
    cudaGetSymbolAddress((void**)&colsrc, g_colsrc);
    cudaGetSymbolAddress((void**)&scanstate, g_scanstate);

    const int gemmBlocks    = (M + 127) / 128;
    const int edgeBlocks    = (E + 255) / 256;
    const int gather128Blks = (M * 16 + 255) / 256;
    const int gather64Blks  = (M * 8 + 255) / 256;
    const int scanBlocks    = (M + 255) / 256;
    const int NXB           = (M * 32 + 255) / 256;   // x16 float4 blocks

    // ---- zero degi, then merged prep (includes count_deg) ----
    cudaMemsetAsync(degi, 0, (size_t)MAXN * sizeof(int));
    prep_all_kernel<<<NXB + 321 + edgeBlocks, 256>>>(
        x, x16, M * 32,
        Ws0, Wn0, bt0,
        Ws1, Wn1, bt1,
        Ws2, Wn2, bt2c,
        scanstate, dst, degi, E, NXB);

    // ---- CSR: scan + cursor-free fill ----
    launch_pdl(scan_fused_kernel, scanBlocks, (const int*)degi, scanstate,
               rowstart, invdeg, M);
    launch_pdl(fill_kernel, edgeBlocks, src, dst, (const int*)rowstart,
               degi, colsrc, E);

    // ---- layer 0: h1 = relu(x@Ws0 + agg(x)@Wn0 + b0) ----
    launch_pdl(gather_kernel, gather128Blks, (const __half*)x16,
               (const int*)rowstart, (const int*)colsrc,
               (const float*)invdeg, agg, M);
    launch_pdl(gemm_f16_kernel<128, true, true, true, false>, gemmBlocks,
               (const __half*)x16, (const __half*)agg, (const __half*)bt0,
               b0, h1, (float*)nullptr, M);

    // ---- layer 1 ----
    launch_pdl(gather_kernel, gather128Blks, (const __half*)h1,
               (const int*)rowstart, (const int*)colsrc,
               (const float*)invdeg, agg, M);
    launch_pdl(gemm_f16_kernel<128, true, true, true, false>, gemmBlocks,
               (const __half*)h1, (const __half*)agg, (const __half*)bt1,
               b1, h2, (float*)nullptr, M);

    // ---- layer 2: [y2|p2] = h2 @ [Wn2|Ws2]; out = p2 + b2 + mean y2[src] ----
    launch_pdl(gemm_f16_kernel<128, false, false, false, true>, gemmBlocks,
               (const __half*)h2, (const __half*)nullptr, (const __half*)bt2c,
               (const float*)nullptr, y2, out, M);
    launch_pdl(gather64_final_kernel, gather64Blks, (const __half*)y2,
               (const int*)rowstart, (const int*)colsrc,
               (const float*)invdeg, b2, out, M);
}